// round 15
// baseline (speedup 1.0000x reference)
#include <cuda_runtime.h>
#include <cstdint>

// CTC forward loss, B=32, T=2048, V=1024, S=256. Single kernel.
// 32 CTAs x 256 threads (8 warps), one batch per CTA. Thread p owns pair
// p (ext s=2p+1 token aT, s=2p+2 blank aB) with per-thread binary
// exponent K (stored*2^K = true; proven in R14). FUSED 2-STEP iteration:
// step A updates own pair AND redundantly pair p-1 (inputs shfl_up 1,2);
// step B is then fully thread-local. ONE barrier / cp_wait / bnd
// round-trip per 2 steps. Emits ex2'd at prefetch (off dependency chain).
// Thread 0 carries ext pos 0 (a0) in its own K domain.

#define TT 2048
#define VV 1024
#define SS 256
#define BB 32
#define STAGES 8
#define NTHREADS 256
#define LOG2E 1.4426950408889634f
#define LN2   0.6931471805599453f

__device__ float g_losses[BB];
__device__ unsigned int g_done;   // zero-init; self-resetting

__device__ __forceinline__ void cp_async16(uint32_t smem_addr, const void* gmem) {
    asm volatile("cp.async.cg.shared.global [%0], [%1], 16;\n"
                 :: "r"(smem_addr), "l"(gmem));
}
__device__ __forceinline__ void cp_commit() {
    asm volatile("cp.async.commit_group;\n" ::: "memory");
}
template <int N>
__device__ __forceinline__ void cp_wait() {
    asm volatile("cp.async.wait_group %0;\n" :: "n"(N) : "memory");
}
__device__ __forceinline__ float ex2(float x) {
    float y; asm("ex2.approx.ftz.f32 %0, %1;" : "=f"(y) : "f"(x)); return y;
}

// Merge inflow (uT,uB,Ku) into pair (aT,aB,K): frontier adoption +
// power-of-2 domain alignment, then one linear DP step with emits eT,eB.
__device__ __forceinline__ void combine(
    float& aT, float& aB, int& K,
    float uT, float uB, int Ku,
    const float repf, const float eT, const float eB)
{
    const bool pz = (aT == 0.0f) && (aB == 0.0f);
    int Ke = pz ? Ku : K;
    int d  = Ku - Ke;
    if (d > 126) { aT = 0.0f; aB = 0.0f; Ke = Ku; d = 0; }  // own negligible
    const bool nz = (uT == 0.0f) && (uB == 0.0f);
    const float s = (nz || d < -126) ? 0.0f
                                     : __int_as_float((127 + d) << 23);
    K = Ke;
    const float nT = eT * fmaf(fmaf(repf, uT, uB), s, aT);
    const float nB = eB * (aB + aT);
    aT = nT; aB = nB;
}

// Renorm (aT,aB,extra) by exact power of 2 so max is in [0.5,1).
// Returns the applied scale (1.0 if all zero).
__device__ __forceinline__ float renorm2(float& aT, float& aB, int& K,
                                         const float extra)
{
    const float mx = fmaxf(fmaxf(aT, aB), extra);
    const int be = (__float_as_int(mx) >> 23) & 255;
    if (be == 0) return 1.0f;
    K += be - 126;
    const float sc = __int_as_float((253 - be) << 23);
    aT *= sc; aB *= sc;
    return sc;
}

__global__ void __launch_bounds__(NTHREADS, 1)
ctc_fused(const float* __restrict__ lp,     // [B, T, V]
          const int* __restrict__ tok,      // [B, S]
          const int* __restrict__ tlens,    // [B]
          const int* __restrict__ slens,    // [B]
          float* __restrict__ out) {
    __shared__ float rows[STAGES][VV];      // 32 KB streamed log-prob rows
    __shared__ float sbT[2][16], sbB[2][16];
    __shared__ int   sbK[2][16];            // pairs 32w+30, 32w+31 per warp

    const int b    = blockIdx.x;
    const int tid  = threadIdx.x;
    const int lane = tid & 31;
    const int w    = tid >> 5;
    const int Tl   = tlens[b];
    const int Sl   = slens[b];
    const float* lpb = lp + (size_t)b * TT * VV;

    const int p  = tid;
    const int L  = tok[b * SS + p];
    const int Lh = (p >= 1) ? tok[b * SS + p - 1] : 0;   // halo pair label
    const int Lq = (p >= 2) ? tok[b * SS + p - 2] : 0;
    const float repO = ((p >= 1) && (L  != Lh)) ? 1.0f : 0.0f;
    const float repH = ((p >= 2) && (Lh != Lq)) ? 1.0f : 0.0f;

    // Prologue: rows 0..6 in groups {0,1}{2,3}{4,5}{6}.
    #pragma unroll
    for (int st = 0; st < 7; ++st) {
        cp_async16((uint32_t)__cvta_generic_to_shared(&rows[st][tid * 4]),
                   lpb + (size_t)st * VV + tid * 4);
        if (st == 1 || st == 3 || st == 5 || st == 6) cp_commit();
    }
    cp_wait<1>();            // rows 0..5 resident
    __syncthreads();

    // t = 0 init (linear; stored*2^K = true; K = 0).
    float aT = 0.0f, aB = 0.0f, a0 = 0.0f;
    int   K  = 0;
    if (tid == 0) {
        a0 = ex2(rows[0][0] * LOG2E);        // alpha[0]
        aT = ex2(rows[0][L] * LOG2E);        // alpha[1]
    }

    // Emits for iter 0 (step A = row 1, step B = row 2), linear.
    float eBA = ex2(rows[1][0]  * LOG2E);
    float eTA = ex2(rows[1][L]  * LOG2E);
    float eHA = ex2(rows[1][Lh] * LOG2E);
    float eBB = ex2(rows[2][0]  * LOG2E);
    float eTB = ex2(rows[2][L]  * LOG2E);

    if (lane >= 30) {                        // publish t=0 state (parity 0)
        sbT[0][2 * w + lane - 30] = aT;
        sbB[0][2 * w + lane - 30] = aB;
        sbK[0][2 * w + lane - 30] = K;
    }

    const int nf = Tl >> 1;                  // fused iterations
    #pragma unroll 1
    for (int f = 0; f < nf; ++f) {
        cp_wait<1>();
        __syncthreads();                     // rows + bnd(par) visible
        const int par  = f & 1;
        const int wpar = par ^ 1;

        // Pre-step neighbor state (time 2f).
        float u1T = __shfl_up_sync(0xffffffffu, aT, 1);
        float u1B = __shfl_up_sync(0xffffffffu, aB, 1);
        int   K1  = __shfl_up_sync(0xffffffffu, K, 1);
        float u2T = __shfl_up_sync(0xffffffffu, aT, 2);
        float u2B = __shfl_up_sync(0xffffffffu, aB, 2);
        int   K2  = __shfl_up_sync(0xffffffffu, K, 2);
        const float a0b = __shfl_sync(0xffffffffu, a0, 0);
        const int   K0b = __shfl_sync(0xffffffffu, K, 0);
        if (lane == 0) {
            if (w) {
                u1T = sbT[par][2 * w - 1]; u1B = sbB[par][2 * w - 1];
                K1  = sbK[par][2 * w - 1];
                u2T = sbT[par][2 * w - 2]; u2B = sbB[par][2 * w - 2];
                K2  = sbK[par][2 * w - 2];
            } else {
                u1T = 0.0f; u1B = a0;  K1 = K;   // pseudo-pair (0, a0)
                u2T = 0.0f; u2B = 0.0f; K2 = K;
            }
        } else if (lane == 1) {
            if (w) {
                u2T = sbT[par][2 * w - 1]; u2B = sbB[par][2 * w - 1];
                K2  = sbK[par][2 * w - 1];
            } else {
                u2T = 0.0f; u2B = a0b; K2 = K0b; // pair -1 = (0, a0)
            }
        }

        // Halo = pair p-1 pre-state.
        float hT = u1T, hB = u1B; int Kh = K1;

        // ---- Step A (t = 2f+1) ----
        combine(aT, aB, K, u1T, u1B, K1, repO, eTA, eBA);   // own
        a0 *= eBA;
        const float scA = renorm2(aT, aB, K, (tid == 0) ? a0 : 0.0f);
        a0 *= scA;
        combine(hT, hB, Kh, u2T, u2B, K2, repH, eHA, eBA);  // halo (no renorm)

        // ---- Step B (t = 2f+2), guarded (CTA-uniform) ----
        if (2 * f + 2 < Tl) {
            combine(aT, aB, K, hT, hB, Kh, repO, eTB, eBB);
            a0 *= eBB;
            const float scB = renorm2(aT, aB, K, (tid == 0) ? a0 : 0.0f);
            a0 *= scB;
        }

        if (lane >= 30) {                    // publish state (time 2f+2)
            sbT[wpar][2 * w + lane - 30] = aT;
            sbB[wpar][2 * w + lane - 30] = aB;
            sbK[wpar][2 * w + lane - 30] = K;
        }

        // Prefetch emits for iter f+1 (rows 2f+3, 2f+4; clamped, resident).
        {
            int rA = 2 * f + 3; if (rA > Tl - 1) rA = Tl - 1;
            int rB = 2 * f + 4; if (rB > Tl - 1) rB = Tl - 1;
            const float* ra = rows[rA & (STAGES - 1)];
            const float* rb = rows[rB & (STAGES - 1)];
            eBA = ex2(ra[0]  * LOG2E);
            eTA = ex2(ra[L]  * LOG2E);
            eHA = ex2(ra[Lh] * LOG2E);
            eBB = ex2(rb[0]  * LOG2E);
            eTB = ex2(rb[L]  * LOG2E);
        }

        // Stream rows 2f+7, 2f+8 (skip past end; commit group always).
        {
            const int r1 = 2 * f + 7;
            if (r1 < Tl)
                cp_async16((uint32_t)__cvta_generic_to_shared(
                               &rows[r1 & (STAGES - 1)][tid * 4]),
                           lpb + (size_t)r1 * VV + tid * 4);
            const int r2 = 2 * f + 8;
            if (r2 < Tl)
                cp_async16((uint32_t)__cvta_generic_to_shared(
                               &rows[r2 & (STAGES - 1)][tid * 4]),
                           lpb + (size_t)r2 * VV + tid * 4);
        }
        cp_commit();
    }

    // Loss: thread Sl-1 holds alpha[2Sl-1]=aT, alpha[2Sl]=aB (x 2^K).
    if (tid == Sl - 1) {
        const float s = aT + aB;
        float loss = -((float)K * LN2 + __logf(s));
        if (!(loss <= 1e29f)) loss = 0.0f;   // s==0 -> inf -> 0
        g_losses[b] = loss / (float)Sl;
        __threadfence();
    }
    __syncthreads();

    // Last-block deterministic reduction (fixed order).
    if (tid == 0) {
        __threadfence();
        const unsigned v = atomicAdd(&g_done, 1u);
        if (v == BB - 1) {
            __threadfence();
            float acc = 0.0f;
            #pragma unroll
            for (int i = 0; i < BB; ++i) acc += g_losses[i];
            out[0] = acc / (float)BB;
            atomicExch(&g_done, 0u);
        }
    }
}

extern "C" void kernel_launch(void* const* d_in, const int* in_sizes, int n_in,
                              void* d_out, int out_size) {
    const float* lp    = (const float*)d_in[0];  // [B,T,V] f32
    const int*   tok   = (const int*)d_in[1];    // [B,S]   i32
    const int*   tlens = (const int*)d_in[2];    // [B]     i32
    const int*   slens = (const int*)d_in[3];    // [B]     i32
    float* out = (float*)d_out;

    ctc_fused<<<BB, NTHREADS>>>(lp, tok, tlens, slens, out);
}

// round 17
// speedup vs baseline: 1.5698x; 1.5698x over previous
#include <cuda_runtime.h>
#include <cstdint>

// CTC forward loss, B=32, T=2048, V=1024, S=256. Single kernel.
// 32 CTAs x 256 threads (8 warps). Thread p owns pair p (ext token
// s=2p+1 -> aT, blank s=2p+2 -> aB); thread 0 also ext pos 0 (a0).
// FUSED 2 STEPS PER BARRIER: step A via shfl_up of (aT,aB); step B via a
// SECOND shfl_up of the step-A results. Only lane 0 lacks its step-B
// neighbor -> it alone redundantly computes pair 32w-1's step-A update
// from warp w-1's published lanes 30,31 (bnd, parity double-buffered).
// log2-domain LSE (raw ex2/lg2). Rows streamed via 16-deep cp.async ring
// (1 commit group / iter, wait<4> -> 10-step DRAM lead); emits
// prefetched one iteration ahead into registers.

#define TT 2048
#define VV 1024
#define SS 256
#define BB 32
#define NEGF (-1e30f)
#define STAGES 16
#define NTHREADS 256
#define LOG2E 1.4426950408889634f
#define LN2   0.6931471805599453f

__device__ float g_losses[BB];
__device__ unsigned int g_done;   // zero-init; self-resetting

__device__ __forceinline__ void cp_async16(uint32_t smem_addr, const void* gmem) {
    asm volatile("cp.async.cg.shared.global [%0], [%1], 16;\n"
                 :: "r"(smem_addr), "l"(gmem));
}
__device__ __forceinline__ void cp_commit() {
    asm volatile("cp.async.commit_group;\n" ::: "memory");
}
template <int N>
__device__ __forceinline__ void cp_wait() {
    asm volatile("cp.async.wait_group %0;\n" :: "n"(N) : "memory");
}
__device__ __forceinline__ float ex2(float x) {
    float y; asm("ex2.approx.ftz.f32 %0, %1;" : "=f"(y) : "f"(x)); return y;
}
__device__ __forceinline__ float lg2(float x) {
    float y; asm("lg2.approx.ftz.f32 %0, %1;" : "=f"(y) : "f"(x)); return y;
}
__device__ __forceinline__ float lse2_2(float a, float b) {
    const float m  = fmaxf(a, b);
    const float lo = fminf(a, b);
    return m + lg2(1.0f + ex2(lo - m));
}
__device__ __forceinline__ float lse3_2(float x0, float x1, float x2) {
    const float lo1 = fminf(x0, x1);
    const float hi1 = fmaxf(x0, x1);
    const float m   = fmaxf(hi1, x2);
    const float o2  = fminf(hi1, x2);
    return m + lg2(1.0f + ex2(lo1 - m) + ex2(o2 - m));
}

__global__ void __launch_bounds__(NTHREADS, 1)
ctc_fused(const float* __restrict__ lp,     // [B, T, V]
          const int* __restrict__ tok,      // [B, S]
          const int* __restrict__ tlens,    // [B]
          const int* __restrict__ slens,    // [B]
          float* __restrict__ out) {
    extern __shared__ float smem[];
    float (*rows)[VV] = (float (*)[VV])smem;      // [STAGES][VV] = 64 KB
    float* bnd = smem + STAGES * VV;              // [2][8][4]

    const int b    = blockIdx.x;
    const int tid  = threadIdx.x;
    const int lane = tid & 31;
    const int w    = tid >> 5;
    const int Tl   = tlens[b];
    const int Sl   = slens[b];
    const float* lpb = lp + (size_t)b * TT * VV;

    const int L  = tok[b * SS + tid];
    const int Lh = (tid >= 1) ? tok[b * SS + tid - 1] : 0;
    const int Lq = (tid >= 2) ? tok[b * SS + tid - 2] : 0;
    const bool rep  = (tid >= 1) && (L  != Lh);
    const bool repH = (tid >= 2) && (Lh != Lq);

    // Prologue: rows 0..12 in 7 groups {0,1}{2,3}...{10,11}{12}.
    #pragma unroll
    for (int st = 0; st < 13; ++st) {
        cp_async16((uint32_t)__cvta_generic_to_shared(&rows[st][tid * 4]),
                   lpb + (size_t)st * VV + tid * 4);
        if ((st & 1) || st == 12) cp_commit();
    }
    cp_wait<4>();            // rows 0..5 resident
    __syncthreads();

    // t = 0 init (log2 domain).
    float aT = NEGF, aB = NEGF, a0 = NEGF;
    if (tid == 0) {
        a0 = rows[0][0] * LOG2E;             // alpha[0]
        aT = rows[0][L] * LOG2E;             // alpha[1]
    }

    // Emits for iter 0 (step A = row 1, step B = row 2).
    float eBA = rows[1][0]  * LOG2E;
    float eTA = rows[1][L]  * LOG2E;
    float eHA = rows[1][Lh] * LOG2E;
    float eBB = rows[2][0]  * LOG2E;
    float eTB = rows[2][L]  * LOG2E;

    if (lane >= 30) {                        // publish t=0 state -> buffer 0
        bnd[0 * 32 + w * 4 + (lane - 30) * 2 + 0] = aT;
        bnd[0 * 32 + w * 4 + (lane - 30) * 2 + 1] = aB;
    }

    const int nf = Tl >> 1;
    #pragma unroll 1
    for (int f = 0; f < nf; ++f) {
        __syncthreads();                     // bnd[par] + streamed rows visible
        const int par  = f & 1;
        const int wpar = par ^ 1;

        // ---- Step A (t = 2f+1) ----
        float u1T = __shfl_up_sync(0xffffffffu, aT, 1);
        float u1B = __shfl_up_sync(0xffffffffu, aB, 1);
        float h2T = NEGF, h2B = NEGF;
        if (lane == 0) {
            if (w) {
                u1T = bnd[par * 32 + (w - 1) * 4 + 2];  // pair 32w-1
                u1B = bnd[par * 32 + (w - 1) * 4 + 3];
                h2T = bnd[par * 32 + (w - 1) * 4 + 0];  // pair 32w-2
                h2B = bnd[par * 32 + (w - 1) * 4 + 1];
            } else {
                u1T = NEGF; u1B = a0;
            }
        }
        const float nT = eTA + lse3_2(aT, u1B, rep ? u1T : NEGF);
        const float nB = eBA + lse2_2(aB, aT);
        const float a0A = a0 + eBA;          // thread 0 meaningful

        // Halo: pair 32w-1's step-A update (lane 0, w>0 only).
        float hT = NEGF, hB = NEGF;
        if (lane == 0 && w > 0) {
            hT = eHA + lse3_2(u1T, h2B, repH ? h2T : NEGF);
            hB = eBA + lse2_2(u1B, u1T);
        }

        // ---- Step B (t = 2f+2) ----
        float v1T = __shfl_up_sync(0xffffffffu, nT, 1);
        float v1B = __shfl_up_sync(0xffffffffu, nB, 1);
        if (lane == 0) {
            if (w) { v1T = hT;   v1B = hB;  }
            else   { v1T = NEGF; v1B = a0A; }
        }
        if (2 * f + 2 < Tl) {                // CTA-uniform guard
            aT = eTB + lse3_2(nT, v1B, rep ? v1T : NEGF);
            aB = eBB + lse2_2(nB, nT);
            a0 = a0A + eBB;
        } else {
            aT = nT; aB = nB; a0 = a0A;
        }

        if (lane >= 30) {                    // publish state -> buffer wpar
            bnd[wpar * 32 + w * 4 + (lane - 30) * 2 + 0] = aT;
            bnd[wpar * 32 + w * 4 + (lane - 30) * 2 + 1] = aB;
        }

        // Prefetch emits for iter f+1 (rows 2f+3, 2f+4; clamped, resident).
        {
            int rA = 2 * f + 3; if (rA > Tl - 1) rA = Tl - 1;
            int rB = 2 * f + 4; if (rB > Tl - 1) rB = Tl - 1;
            const float* ra = rows[rA & (STAGES - 1)];
            const float* rb = rows[rB & (STAGES - 1)];
            eBA = ra[0]  * LOG2E;
            eTA = ra[L]  * LOG2E;
            eHA = ra[Lh] * LOG2E;
            eBB = rb[0]  * LOG2E;
            eTB = rb[L]  * LOG2E;
        }

        // Stream rows 2f+13, 2f+14 (skip past end; commit group always).
        {
            const int r1 = 2 * f + 13;
            if (r1 < Tl)
                cp_async16((uint32_t)__cvta_generic_to_shared(
                               &rows[r1 & (STAGES - 1)][tid * 4]),
                           lpb + (size_t)r1 * VV + tid * 4);
            const int r2 = 2 * f + 14;
            if (r2 < Tl)
                cp_async16((uint32_t)__cvta_generic_to_shared(
                               &rows[r2 & (STAGES - 1)][tid * 4]),
                           lpb + (size_t)r2 * VV + tid * 4);
        }
        cp_commit();
        cp_wait<4>();
    }

    // Loss: thread Sl-1 holds alpha[2Sl-1]=aT, alpha[2Sl]=aB (log2 domain).
    if (tid == Sl - 1) {
        float loss = -lse2_2(aB, aT) * LN2;
        if (!(loss <= 1e29f)) loss = 0.0f;
        g_losses[b] = loss / (float)Sl;
        __threadfence();
    }
    __syncthreads();

    // Last-block deterministic reduction (fixed order).
    if (tid == 0) {
        __threadfence();
        const unsigned v = atomicAdd(&g_done, 1u);
        if (v == BB - 1) {
            __threadfence();
            float acc = 0.0f;
            #pragma unroll
            for (int i = 0; i < BB; ++i) acc += g_losses[i];
            out[0] = acc / (float)BB;
            atomicExch(&g_done, 0u);
        }
    }
}

extern "C" void kernel_launch(void* const* d_in, const int* in_sizes, int n_in,
                              void* d_out, int out_size) {
    const float* lp    = (const float*)d_in[0];  // [B,T,V] f32
    const int*   tok   = (const int*)d_in[1];    // [B,S]   i32
    const int*   tlens = (const int*)d_in[2];    // [B]     i32
    const int*   slens = (const int*)d_in[3];    // [B]     i32
    float* out = (float*)d_out;

    const int smem_bytes = (STAGES * VV + 64) * (int)sizeof(float);
    cudaFuncSetAttribute(ctc_fused, cudaFuncAttributeMaxDynamicSharedMemorySize,
                         smem_bytes);
    ctc_fused<<<BB, NTHREADS, smem_bytes>>>(lp, tok, tlens, slens, out);
}